// round 2
// baseline (speedup 1.0000x reference)
#include <cuda_runtime.h>
#include <cstdint>

// NoiseLinear: out[b,o] = sum_i x[b,i]*w[o,i] + bias[o]
//                       + 0.1 * sum_i eps[b,o,i]*w[o,i]*x[b,i]
// eps reproduced for JAX partitionable threefry (verified rel_err 5.9e-7 in R1).
// R2: pipe-balance the threefry adds onto the IMAD/FMA pipe; shave issue slots.

#define B_DIM  64
#define IN_DIM 1024
#define OUT_DIM 4096
#define NOISE_F 0.1f

// Opaque 1: loaded from memory so ptxas cannot strength-reduce IMAD -> IADD3.
__device__ unsigned int g_one = 1u;

// a + b forced onto the FMA pipe as IMAD (a*one + b).
#define MADD(d, a, b)                                                   \
    asm("mad.lo.u32 %0, %1, %2, %3;" : "=r"(d) : "r"(a), "r"(one), "r"(b))

struct TFK {
    uint32_t ks1, ks2, ks2p1, ks1p3, ks2p4, one;
};

__device__ __forceinline__ void tf2x32(const TFK& k, uint32_t basek, uint32_t i,
                                       uint32_t& o0, uint32_t& o1) {
    const uint32_t one = k.one;
    uint32_t x0, x1;
    // x1_init = counter + ks1 = basek + i (basek = flat_base + ks1, precomputed)
    MADD(x1, basek, i);
    // round 1: x0 = 0 + x1
    x0 = x1;
    x1 = __funnelshift_l(x1, x1, 13); x1 ^= x0;
#define TF_R(r) { MADD(x0, x0, x1); x1 = __funnelshift_l(x1, x1, (r)); x1 ^= x0; }
    TF_R(15) TF_R(26) TF_R(6)
    MADD(x0, x0, k.ks1);  MADD(x1, x1, k.ks2p1);
    TF_R(17) TF_R(29) TF_R(16) TF_R(24)
    MADD(x0, x0, k.ks2);  x1 += 2u;            // + ks0(=0) + 2
    TF_R(13) TF_R(15) TF_R(26) TF_R(6)
    /* x0 += ks0 = 0 */   MADD(x1, x1, k.ks1p3);
    TF_R(17) TF_R(29) TF_R(16) TF_R(24)
    MADD(x0, x0, k.ks1);  MADD(x1, x1, k.ks2p4);
    TF_R(13) TF_R(15) TF_R(26) TF_R(6)
    MADD(x0, x0, k.ks2);  x1 += 5u;            // + ks0(=0) + 5
#undef TF_R
    o0 = x0; o1 = x1;
}

// bits -> N(0,1) sample, sqrt(2) pre-folded into the Giles coefficients.
__device__ __forceinline__ float bits_to_normal(uint32_t bits) {
    // v in [1,2); u = 2v - 3 = (2f - 0.99999994) - 2^-24  (negligible shift)
    float v = __uint_as_float((bits >> 9) + 0x3f800000u);
    float u = __fmaf_rn(v, 2.0f, -3.0f);
    u = fmaxf(u, -0.99999994f);                   // keep 1-u^2 > 0
    float t = __fmaf_rn(u, -u, 1.0f);             // 1 - u^2
    float L = __log2f(t);
    float w = __fmul_rn(L, -0.69314718f);         // -log(1-u^2)
    float p;
    if (w < 5.0f) {
        w -= 2.5f;
        p = 3.9742549e-08f;
        p = __fmaf_rn(p, w, 4.8546651e-07f);
        p = __fmaf_rn(p, w, -4.9828354e-06f);
        p = __fmaf_rn(p, w, -6.2105158e-06f);
        p = __fmaf_rn(p, w, 3.0912028e-04f);
        p = __fmaf_rn(p, w, -1.7730373e-03f);
        p = __fmaf_rn(p, w, -5.9081330e-03f);
        p = __fmaf_rn(p, w, 3.4880532e-01f);
        p = __fmaf_rn(p, w, 2.1233136e+00f);
    } else {
        w = __fsqrt_rn(w) - 3.0f;
        p = -2.8314768e-04f;
        p = __fmaf_rn(p, w, 1.4276563e-04f);
        p = __fmaf_rn(p, w, 1.9082642e-03f);
        p = __fmaf_rn(p, w, -5.1950162e-03f);
        p = __fmaf_rn(p, w, 8.1168864e-03f);
        p = __fmaf_rn(p, w, -1.0779783e-02f);
        p = __fmaf_rn(p, w, 1.3348632e-02f);
        p = __fmaf_rn(p, w, 1.4165810e+00f);
        p = __fmaf_rn(p, w, 4.0064343e+00f);
    }
    return __fmul_rn(p, u);                        // sqrt(2)*erfinv(u)
}

// One warp per (b-pair, o). b-pair = (bp, bp+32). Lanes stride IN=1024 with
// float4 loads; 8 independent threefry chains per loop body for ILP.
__global__ void __launch_bounds__(256, 4)
noise_linear_kernel(const float* __restrict__ x, const float* __restrict__ w,
                    const float* __restrict__ bias, const int* __restrict__ seedp,
                    float* __restrict__ out) {
    TFK k;
    k.one = *(volatile const unsigned int*)&g_one;   // opaque 1
    k.ks1 = (uint32_t)seedp[0];
    k.ks2 = k.ks1 ^ 0x1BD11BDAu;
    k.ks2p1 = k.ks2 + 1u;
    k.ks1p3 = k.ks1 + 3u;
    k.ks2p4 = k.ks2 + 4u;

    const int gw   = blockIdx.x * (blockDim.x >> 5) + (threadIdx.x >> 5);
    const int lane = threadIdx.x & 31;
    const int o  = gw & (OUT_DIM - 1);
    const int bp = gw >> 12;                 // 0..31
    const int b0 = bp, b1 = bp + 32;

    const float4* __restrict__ wrow  = (const float4*)(w + (size_t)o  * IN_DIM);
    const float4* __restrict__ x0row = (const float4*)(x + (size_t)b0 * IN_DIM);
    const float4* __restrict__ x1row = (const float4*)(x + (size_t)b1 * IN_DIM);

    const uint32_t base0 = (uint32_t)b0 * (OUT_DIM * IN_DIM) + (uint32_t)o * IN_DIM;
    const uint32_t bk0 = base0 + k.ks1;                      // fold +ks1 into base
    const uint32_t bk1 = bk0 + 32u * (OUT_DIM * IN_DIM);

    float lin0 = 0.f, lin1 = 0.f, n0 = 0.f, n1 = 0.f;

#pragma unroll 1
    for (int ii = 0; ii < IN_DIM / 128; ++ii) {     // 8 iterations
        const int vec = ii * 32 + lane;             // float4 index in the row
        const float4 w4 = __ldg(wrow  + vec);
        const float4 a4 = __ldg(x0row + vec);
        const float4 b4 = __ldg(x1row + vec);
        const uint32_t ibase = (uint32_t)vec * 4u;
#pragma unroll
        for (int j = 0; j < 4; ++j) {
            const float wv = (&w4.x)[j];
            const float av = (&a4.x)[j];
            const float bv = (&b4.x)[j];
            const uint32_t i = ibase + (uint32_t)j;

            const float t0 = __fmul_rn(wv, av);
            const float t1 = __fmul_rn(wv, bv);
            lin0 = __fadd_rn(lin0, t0);
            lin1 = __fadd_rn(lin1, t1);

            uint32_t r0a, r0b, r1a, r1b;
            tf2x32(k, bk0, i, r0a, r0b);
            tf2x32(k, bk1, i, r1a, r1b);
            const float e0 = bits_to_normal(r0a ^ r0b);
            const float e1 = bits_to_normal(r1a ^ r1b);

            n0 = __fmaf_rn(e0, t0, n0);
            n1 = __fmaf_rn(e1, t1, n1);
        }
    }

    // warp butterfly reduce (4 accumulators)
#pragma unroll
    for (int off = 16; off > 0; off >>= 1) {
        lin0 += __shfl_xor_sync(0xFFFFFFFFu, lin0, off);
        lin1 += __shfl_xor_sync(0xFFFFFFFFu, lin1, off);
        n0   += __shfl_xor_sync(0xFFFFFFFFu, n0,   off);
        n1   += __shfl_xor_sync(0xFFFFFFFFu, n1,   off);
    }

    if (lane == 0) {
        const float bz = __ldg(bias + o);
        out[(size_t)b0 * OUT_DIM + o] = lin0 + bz + NOISE_F * n0;
        out[(size_t)b1 * OUT_DIM + o] = lin1 + bz + NOISE_F * n1;
    }
}

extern "C" void kernel_launch(void* const* d_in, const int* in_sizes, int n_in,
                              void* d_out, int out_size) {
    const float* x    = (const float*)d_in[0];
    const float* w    = (const float*)d_in[1];
    const float* bias = (const float*)d_in[2];
    const int*   seed = (const int*)d_in[3];
    float* out = (float*)d_out;

    // 32 b-pairs * 4096 outputs = 131072 warps; 8 warps/block -> 16384 blocks
    noise_linear_kernel<<<16384, 256>>>(x, w, bias, seed, out);
}